// round 1
// baseline (speedup 1.0000x reference)
#include <cuda_runtime.h>
#include <math.h>

// Problem constants (fixed by the registry problem):
// T=4, B=8, H=W=32 -> N=1024, C=512, NH=8, D=64, TB=32, M=TB*N=32768
#define MM 32768
#define O3 1536
#define CC 512

// ---------------- scratch (static __device__, no allocation) ----------------
__device__ float g_Y [(size_t)O3 * MM];   // qkv pre-activations   [o][m], o in [0,1536)
__device__ float g_S [(size_t)O3 * MM];   // qkv spikes            [o][m]
__device__ float g_KV[256 * 64 * 64];     // kv per (t,b,h)        [g][d][e]
__device__ float g_A [(size_t)CC * MM];   // attention pre-LIF     [c][m]
__device__ float g_Sa[(size_t)CC * MM];   // attention spikes      [c][m]
__device__ float g_P [(size_t)CC * MM];   // proj pre-activations  [c][m]
__device__ float g_scale [O3], g_shift [O3];
__device__ float g_scale2[CC], g_shift2[CC];

// ---------------- GEMM1: g_Y[o][m] = sum_c W[o][c] * X[m][c] ----------------
// X row-major [32768, 512] (c contiguous); W row-major [512,512] per branch.
__global__ __launch_bounds__(256) void gemm_qkv(
    const float* __restrict__ Wq, const float* __restrict__ Wk,
    const float* __restrict__ Wv, const float* __restrict__ X)
{
    __shared__ float As[16][132];
    __shared__ float Bs[16][132];
    int m0 = blockIdx.x * 128;
    int o0 = blockIdx.y * 128;
    const float* W = Wq; int ob = o0;
    if (o0 >= 1024)      { W = Wv; ob = o0 - 1024; }
    else if (o0 >= 512)  { W = Wk; ob = o0 - 512;  }

    int tid = threadIdx.x;
    int tx = tid & 15, ty = tid >> 4;
    int lr = tid >> 2;            // 0..63
    int lk = (tid & 3) << 2;      // 0,4,8,12

    float acc[8][8];
#pragma unroll
    for (int i = 0; i < 8; i++)
#pragma unroll
        for (int j = 0; j < 8; j++) acc[i][j] = 0.f;

    for (int k0 = 0; k0 < 512; k0 += 16) {
#pragma unroll
        for (int rr = 0; rr < 2; rr++) {
            int r = lr + rr * 64;
            float4 a = *(const float4*)&W[(size_t)(ob + r) * 512 + k0 + lk];
            As[lk+0][r] = a.x; As[lk+1][r] = a.y; As[lk+2][r] = a.z; As[lk+3][r] = a.w;
            float4 b = *(const float4*)&X[(size_t)(m0 + r) * 512 + k0 + lk];
            Bs[lk+0][r] = b.x; Bs[lk+1][r] = b.y; Bs[lk+2][r] = b.z; Bs[lk+3][r] = b.w;
        }
        __syncthreads();
#pragma unroll
        for (int kk = 0; kk < 16; kk++) {
            float ar[8], br[8];
            *(float4*)&ar[0] = *(const float4*)&As[kk][ty*8];
            *(float4*)&ar[4] = *(const float4*)&As[kk][ty*8+4];
            *(float4*)&br[0] = *(const float4*)&Bs[kk][tx*8];
            *(float4*)&br[4] = *(const float4*)&Bs[kk][tx*8+4];
#pragma unroll
            for (int i = 0; i < 8; i++)
#pragma unroll
                for (int j = 0; j < 8; j++)
                    acc[i][j] = fmaf(ar[i], br[j], acc[i][j]);
        }
        __syncthreads();
    }
#pragma unroll
    for (int i = 0; i < 8; i++) {
        size_t row = (size_t)(o0 + ty*8 + i) * MM + m0 + tx*8;
        *(float4*)&g_Y[row]   = make_float4(acc[i][0], acc[i][1], acc[i][2], acc[i][3]);
        *(float4*)&g_Y[row+4] = make_float4(acc[i][4], acc[i][5], acc[i][6], acc[i][7]);
    }
}

// ---------------- GEMM2: g_P[o][m] = sum_c W[o][c] * g_Sa[c][m] -------------
__global__ __launch_bounds__(256) void gemm_proj(const float* __restrict__ W)
{
    __shared__ float As[16][132];
    __shared__ float Bs[16][132];
    int m0 = blockIdx.x * 128;
    int o0 = blockIdx.y * 128;
    int tid = threadIdx.x;
    int tx = tid & 15, ty = tid >> 4;
    int lr = tid >> 2;
    int lk = (tid & 3) << 2;
    int lc = tid >> 5;            // 0..7
    int lm = (tid & 31) << 2;     // 0..124

    float acc[8][8];
#pragma unroll
    for (int i = 0; i < 8; i++)
#pragma unroll
        for (int j = 0; j < 8; j++) acc[i][j] = 0.f;

    for (int k0 = 0; k0 < 512; k0 += 16) {
#pragma unroll
        for (int rr = 0; rr < 2; rr++) {
            int r = lr + rr * 64;
            float4 a = *(const float4*)&W[(size_t)(o0 + r) * 512 + k0 + lk];
            As[lk+0][r] = a.x; As[lk+1][r] = a.y; As[lk+2][r] = a.z; As[lk+3][r] = a.w;
        }
#pragma unroll
        for (int rr = 0; rr < 2; rr++) {
            int c = lc + rr * 8;
            float4 b = *(const float4*)&g_Sa[(size_t)(k0 + c) * MM + m0 + lm];
            *(float4*)&Bs[c][lm] = b;
        }
        __syncthreads();
#pragma unroll
        for (int kk = 0; kk < 16; kk++) {
            float ar[8], br[8];
            *(float4*)&ar[0] = *(const float4*)&As[kk][ty*8];
            *(float4*)&ar[4] = *(const float4*)&As[kk][ty*8+4];
            *(float4*)&br[0] = *(const float4*)&Bs[kk][tx*8];
            *(float4*)&br[4] = *(const float4*)&Bs[kk][tx*8+4];
#pragma unroll
            for (int i = 0; i < 8; i++)
#pragma unroll
                for (int j = 0; j < 8; j++)
                    acc[i][j] = fmaf(ar[i], br[j], acc[i][j]);
        }
        __syncthreads();
    }
#pragma unroll
    for (int i = 0; i < 8; i++) {
        size_t row = (size_t)(o0 + ty*8 + i) * MM + m0 + tx*8;
        *(float4*)&g_P[row]   = make_float4(acc[i][0], acc[i][1], acc[i][2], acc[i][3]);
        *(float4*)&g_P[row+4] = make_float4(acc[i][4], acc[i][5], acc[i][6], acc[i][7]);
    }
}

// -------- BN stats: per-channel mean/var over 32768 elems (fp64 accum) ------
// which=0: g_Y -> g_scale/g_shift ; which=1: g_P -> g_scale2/g_shift2
__global__ __launch_bounds__(256) void bn_stats(int which, int ch0,
    const float* __restrict__ gamma, const float* __restrict__ beta)
{
    const float* Y = which ? g_P : g_Y;
    float* sc = which ? g_scale2 : g_scale;
    float* sf = which ? g_shift2 : g_shift;
    int c  = blockIdx.x;
    int ch = ch0 + c;
    const float* p = Y + (size_t)ch * MM;
    double s = 0.0, ss = 0.0;
    for (int i = threadIdx.x; i < MM; i += 256) {
        float x = p[i];
        s  += (double)x;
        ss += (double)x * (double)x;
    }
    __shared__ double shs[256], shss[256];
    int tid = threadIdx.x;
    shs[tid] = s; shss[tid] = ss;
    __syncthreads();
    for (int o = 128; o > 0; o >>= 1) {
        if (tid < o) { shs[tid] += shs[tid+o]; shss[tid] += shss[tid+o]; }
        __syncthreads();
    }
    if (tid == 0) {
        double mean = shs[0] * (1.0 / (double)MM);
        double var  = shss[0] * (1.0 / (double)MM) - mean * mean;
        double inv  = 1.0 / sqrt(var + 1e-5);
        double g    = (double)gamma[c];
        sc[ch] = (float)(g * inv);
        sf[ch] = (float)((double)beta[c] - mean * g * inv);
    }
}

// -------- LIF over T (tau=2 -> *0.5, hard reset), qkv: vth=1.0 --------------
__global__ __launch_bounds__(256) void lif_qkv()
{
    int ch = blockIdx.x;            // 0..1535
    int b  = blockIdx.y;            // 0..7
    float sc = g_scale[ch], sf = g_shift[ch];
    size_t base = (size_t)ch * MM + (size_t)b * 1024;
    for (int n = threadIdx.x; n < 1024; n += 256) {
        float v = 0.f;
#pragma unroll
        for (int t = 0; t < 4; t++) {
            size_t idx = base + (size_t)t * 8192 + n;
            float xv = g_Y[idx] * sc + sf;
            v = v + (xv - v) * 0.5f;
            bool s = (v >= 1.0f);
            g_S[idx] = s ? 1.f : 0.f;
            if (s) v = 0.f;
        }
    }
}

// -------- attn LIF: vth=0.5, no BN --------
__global__ __launch_bounds__(256) void lif_attn()
{
    int ch = blockIdx.x;            // 0..511
    int b  = blockIdx.y;
    size_t base = (size_t)ch * MM + (size_t)b * 1024;
    for (int n = threadIdx.x; n < 1024; n += 256) {
        float v = 0.f;
#pragma unroll
        for (int t = 0; t < 4; t++) {
            size_t idx = base + (size_t)t * 8192 + n;
            float xv = g_A[idx];
            v = v + (xv - v) * 0.5f;
            bool s = (v >= 0.5f);
            g_Sa[idx] = s ? 1.f : 0.f;
            if (s) v = 0.f;
        }
    }
}

// -------- kv[g][d][e] = sum_n K[d][n] * V[e][n], g=(tb,h), N=1024 ------------
__global__ __launch_bounds__(256) void kv_kernel()
{
    __shared__ float Ks[64][65];
    __shared__ float Vs[64][65];
    int g  = blockIdx.x;            // tb*8 + h
    int tb = g >> 3, h = g & 7;
    int tid = threadIdx.x;
    int tx = tid & 15, ty = tid >> 4;
    size_t kbase = (size_t)(512  + h*64) * MM + (size_t)tb * 1024;
    size_t vbase = (size_t)(1024 + h*64) * MM + (size_t)tb * 1024;
    float acc[4][4];
#pragma unroll
    for (int i = 0; i < 4; i++)
#pragma unroll
        for (int j = 0; j < 4; j++) acc[i][j] = 0.f;

    for (int n0 = 0; n0 < 1024; n0 += 64) {
        for (int i = tid; i < 1024; i += 256) {      // 64 rows x 16 float4
            int d = i >> 4, c4 = (i & 15) << 2;
            float4 kk = *(const float4*)&g_S[kbase + (size_t)d * MM + n0 + c4];
            Ks[d][c4+0]=kk.x; Ks[d][c4+1]=kk.y; Ks[d][c4+2]=kk.z; Ks[d][c4+3]=kk.w;
            float4 vv = *(const float4*)&g_S[vbase + (size_t)d * MM + n0 + c4];
            Vs[d][c4+0]=vv.x; Vs[d][c4+1]=vv.y; Vs[d][c4+2]=vv.z; Vs[d][c4+3]=vv.w;
        }
        __syncthreads();
#pragma unroll
        for (int j = 0; j < 64; j++) {
            float kr[4], vr[4];
#pragma unroll
            for (int i = 0; i < 4; i++) kr[i] = Ks[ty*4+i][j];
#pragma unroll
            for (int i = 0; i < 4; i++) vr[i] = Vs[tx*4+i][j];
#pragma unroll
            for (int i = 0; i < 4; i++)
#pragma unroll
                for (int jj = 0; jj < 4; jj++)
                    acc[i][jj] = fmaf(kr[i], vr[jj], acc[i][jj]);
        }
        __syncthreads();
    }
#pragma unroll
    for (int i = 0; i < 4; i++)
#pragma unroll
        for (int j = 0; j < 4; j++)
            g_KV[(size_t)g*4096 + (ty*4+i)*64 + tx*4 + j] = acc[i][j];
}

// -------- a[c=h*64+e][m] = 0.125 * sum_d kv[d][e] * Q[d][n] ------------------
__global__ __launch_bounds__(256) void attn_a()
{
    __shared__ float KVs[64][68];
    __shared__ float Qs [64][68];
    int n0 = blockIdx.x * 64;       // 16 tiles of n
    int g  = blockIdx.y;            // 256 groups
    int tb = g >> 3, h = g & 7;
    int tid = threadIdx.x;
    int tx = tid & 15, ty = tid >> 4;
    size_t qbase = (size_t)(h*64) * MM + (size_t)tb * 1024 + n0;
    for (int i = tid; i < 1024; i += 256) {
        int d = i >> 4, c4 = (i & 15) << 2;
        *(float4*)&KVs[d][c4] = *(const float4*)&g_KV[(size_t)g*4096 + d*64 + c4];
        *(float4*)&Qs[d][c4]  = *(const float4*)&g_S[qbase + (size_t)d * MM + c4];
    }
    __syncthreads();
    float acc[4][4];
#pragma unroll
    for (int i = 0; i < 4; i++)
#pragma unroll
        for (int j = 0; j < 4; j++) acc[i][j] = 0.f;
#pragma unroll
    for (int d = 0; d < 64; d++) {
        float4 kv4 = *(const float4*)&KVs[d][ty*4];   // e = ty*4..+3
        float4 q4  = *(const float4*)&Qs[d][tx*4];    // n = tx*4..+3
        float kvv[4] = {kv4.x, kv4.y, kv4.z, kv4.w};
        float qv[4]  = {q4.x,  q4.y,  q4.z,  q4.w};
#pragma unroll
        for (int i = 0; i < 4; i++)
#pragma unroll
            for (int j = 0; j < 4; j++)
                acc[i][j] = fmaf(kvv[i], qv[j], acc[i][j]);
    }
#pragma unroll
    for (int i = 0; i < 4; i++) {
        int e = ty*4 + i;
        size_t base = (size_t)(h*64 + e) * MM + (size_t)tb * 1024 + n0 + tx*4;
        *(float4*)&g_A[base] = make_float4(0.125f*acc[i][0], 0.125f*acc[i][1],
                                           0.125f*acc[i][2], 0.125f*acc[i][3]);
    }
}

// -------- final LIF (vth=1.0) + transpose to output [t][b][c][n] -------------
__global__ __launch_bounds__(256) void lif_final(float* __restrict__ out)
{
    int c = blockIdx.x;             // 0..511
    int b = blockIdx.y;             // 0..7
    float sc = g_scale2[c], sf = g_shift2[c];
    for (int n = threadIdx.x; n < 1024; n += 256) {
        float v = 0.f;
#pragma unroll
        for (int t = 0; t < 4; t++) {
            size_t idx = (size_t)c * MM + (size_t)(t*8 + b) * 1024 + n;
            float xv = g_P[idx] * sc + sf;
            v = v + (xv - v) * 0.5f;
            bool s = (v >= 1.0f);
            out[((size_t)(t*8 + b) * 512 + c) * 1024 + n] = s ? 1.f : 0.f;
            if (s) v = 0.f;
        }
    }
}

// ---------------------------------------------------------------------------
extern "C" void kernel_launch(void* const* d_in, const int* in_sizes, int n_in,
                              void* d_out, int out_size)
{
    const float* x   = (const float*)d_in[0];
    const float* q_w = (const float*)d_in[1];
    const float* q_g = (const float*)d_in[2];
    const float* q_b = (const float*)d_in[3];
    const float* k_w = (const float*)d_in[4];
    const float* k_g = (const float*)d_in[5];
    const float* k_b = (const float*)d_in[6];
    const float* v_w = (const float*)d_in[7];
    const float* v_g = (const float*)d_in[8];
    const float* v_b = (const float*)d_in[9];
    const float* p_w = (const float*)d_in[10];
    // d_in[11] = proj_b: added before training-mode BN -> cancels exactly; skipped.
    const float* p_g = (const float*)d_in[12];
    const float* p_b = (const float*)d_in[13];
    float* out = (float*)d_out;

    // 1) fused QKV GEMM: [1536 x 32768]
    gemm_qkv<<<dim3(MM/128, O3/128), 256>>>(q_w, k_w, v_w, x);
    // 2) BN stats per branch
    bn_stats<<<512, 256>>>(0, 0,    q_g, q_b);
    bn_stats<<<512, 256>>>(0, 512,  k_g, k_b);
    bn_stats<<<512, 256>>>(0, 1024, v_g, v_b);
    // 3) LIF -> binary spikes (vth=1.0)
    lif_qkv<<<dim3(O3, 8), 256>>>();
    // 4) kv = K^T V per (t,b,h)
    kv_kernel<<<256, 256>>>();
    // 5) a = Q kv * 0.125
    attn_a<<<dim3(16, 256), 256>>>();
    // 6) attn LIF (vth=0.5)
    lif_attn<<<dim3(CC, 8), 256>>>();
    // 7) proj GEMM
    gemm_proj<<<dim3(MM/128, CC/128), 256>>>(p_w);
    // 8) proj BN stats (bias dropped - cancels)
    bn_stats<<<512, 256>>>(1, 0, p_g, p_b);
    // 9) final LIF + transpose to [T,B,C,H,W]
    lif_final<<<dim3(CC, 8), 256>>>(out);
}